// round 16
// baseline (speedup 1.0000x reference)
#include <cuda_runtime.h>
#include <math_constants.h>

// x: (64, 4096, 256) fp32; top-8 over axis 1 (S), sorted desc -> (64, 8, 256)
#define B_DIM 64
#define S_DIM 4096
#define C_DIM 256
#define K_TOP 8

#define QDIV 16                         // S-segments per channel (one per thread row)
#define SEG (S_DIM / QDIV)              // 256 s-values per thread
#define CPB 16                          // channel-pairs per block (32 channels)
#define NCG (C_DIM / 2 / CPB)           // 8 channel groups
#define GRID1 (B_DIM * NCG)             // 512 blocks x 256 threads

// Compare-exchange keeping max at 'a' (descending order).
__device__ __forceinline__ void ce(float& a, float& b) {
    float hi = fmaxf(a, b);
    float lo = fminf(a, b);
    a = hi; b = lo;
}

// Batcher odd-even mergesort, n=8, 19 CE, descending.
__device__ __forceinline__ void sort8_desc(float (&f)[8]) {
    ce(f[0],f[1]); ce(f[2],f[3]); ce(f[4],f[5]); ce(f[6],f[7]);
    ce(f[0],f[2]); ce(f[1],f[3]); ce(f[4],f[6]); ce(f[5],f[7]);
    ce(f[1],f[2]); ce(f[5],f[6]);
    ce(f[0],f[4]); ce(f[1],f[5]); ce(f[2],f[6]); ce(f[3],f[7]);
    ce(f[2],f[4]); ce(f[3],f[5]);
    ce(f[1],f[2]); ce(f[3],f[4]); ce(f[5],f[6]);
}

// Exact sorted top-8 of the union of two descending-sorted 8-lists.
__device__ __forceinline__ void merge8_desc(float (&t)[8], const float (&g)[8]) {
    #pragma unroll
    for (int i = 0; i < 8; ++i) t[i] = fmaxf(t[i], g[7 - i]);
    ce(t[0],t[4]); ce(t[1],t[5]); ce(t[2],t[6]); ce(t[3],t[7]);
    ce(t[0],t[2]); ce(t[1],t[3]); ce(t[4],t[6]); ce(t[5],t[7]);
    ce(t[0],t[1]); ce(t[2],t[3]); ce(t[4],t[5]); ce(t[6],t[7]);
}

// Single-pass kernel: block = (batch, channel-group of 32 channels).
// Thread (q, cp) streams S-segment q of channel-pair cp, then the block
// merges its 16 segments through shared memory. 4 CTAs/SM -> one full wave.
__global__ __launch_bounds__(256, 4) void kmax_onepass_kernel(
    const float2* __restrict__ x2, float* __restrict__ out)
{
    __shared__ float s_t[256][16];              // per-thread t0|t1 (16 KB)

    const int b  = blockIdx.x >> 3;             // / NCG
    const int cg = blockIdx.x & (NCG - 1);
    const int cp = threadIdx.x & (CPB - 1);     // channel-pair within group
    const int q  = threadIdx.x >> 4;            // S-segment index

    const float2* __restrict__ p =
        x2 + ((size_t)b * S_DIM + (size_t)q * SEG) * (C_DIM / 2) + cg * CPB + cp;

    float t0[8], t1[8];
    #pragma unroll
    for (int i = 0; i < 8; ++i) { t0[i] = -CUDART_INF_F; t1[i] = -CUDART_INF_F; }

    #pragma unroll 1
    for (int s = 0; s < SEG; s += 16) {
        float2 buf[16];
        #pragma unroll
        for (int u = 0; u < 16; ++u)
            buf[u] = __ldcs(p + (size_t)(s + u) * (C_DIM / 2));

        float f[8], g[8];
        // channel .x
        #pragma unroll
        for (int u = 0; u < 8; ++u) { f[u] = buf[u].x; g[u] = buf[u + 8].x; }
        sort8_desc(f); sort8_desc(g);
        merge8_desc(f, g);      // f = sorted top-8 of the 16
        merge8_desc(t0, f);
        // channel .y
        #pragma unroll
        for (int u = 0; u < 8; ++u) { f[u] = buf[u].y; g[u] = buf[u + 8].y; }
        sort8_desc(f); sort8_desc(g);
        merge8_desc(f, g);
        merge8_desc(t1, f);
    }

    // Publish this thread's two sorted top-8s.
    #pragma unroll
    for (int i = 0; i < 8; ++i) {
        s_t[threadIdx.x][i]     = t0[i];
        s_t[threadIdx.x][8 + i] = t1[i];
    }
    __syncthreads();

    // Two warps merge the 16 q-segment records per channel (32 channels).
    if (threadIdx.x < 64) {
        const int rcp  = (threadIdx.x >> 1) & 15;   // channel-pair 0..15
        const int half = threadIdx.x & 1;           // 0 = .x, 1 = .y
        const int dup  = threadIdx.x >> 5;          // warp 0: q 0..7, warp 1: none
        const int off  = half * 8;

        // Split the 15-merge chain across... keep simple: warp0 handles
        // pairs 0..15 (threads 0..31), warp1 idles after publish? No —
        // assign: threads 0..31 -> channels 0..31 directly.
        if (dup == 0) {
            float m[8];
            #pragma unroll
            for (int i = 0; i < 8; ++i) m[i] = s_t[rcp][off + i];   // q = 0
            #pragma unroll
            for (int j = 1; j < QDIV; ++j) {
                float g[8];
                #pragma unroll
                for (int i = 0; i < 8; ++i) g[i] = s_t[j * CPB + rcp][off + i];
                merge8_desc(m, g);
            }

            const int ch = cg * (CPB * 2) + rcp * 2 + half;
            float* __restrict__ o = out + (size_t)b * K_TOP * C_DIM + ch;
            #pragma unroll
            for (int k = 0; k < K_TOP; ++k)
                o[(size_t)k * C_DIM] = m[k];
        }
    }
}

extern "C" void kernel_launch(void* const* d_in, const int* in_sizes, int n_in,
                              void* d_out, int out_size) {
    const float2* x2 = (const float2*)d_in[0];
    float* out = (float*)d_out;
    kmax_onepass_kernel<<<GRID1, 256>>>(x2, out);
}

// round 17
// speedup vs baseline: 1.0406x; 1.0406x over previous
#include <cuda_runtime.h>
#include <math_constants.h>

// x: (64, 4096, 256) fp32; top-8 over axis 1 (S), sorted desc -> (64, 8, 256)
#define B_DIM 64
#define S_DIM 4096
#define C_DIM 256
#define K_TOP 8

#define QDIV 16                         // S-segments per channel
#define SEG (S_DIM / QDIV)              // 256 s-values per thread (proven loop)
#define CPB 32                          // channel-pairs per block (64 channels)
#define NCG (C_DIM / 2 / CPB)           // 4 channel groups
#define GRID1 (B_DIM * NCG)             // 256 blocks x 512 threads
#define NT 512

// Compare-exchange keeping max at 'a' (descending order).
__device__ __forceinline__ void ce(float& a, float& b) {
    float hi = fmaxf(a, b);
    float lo = fminf(a, b);
    a = hi; b = lo;
}

// Batcher odd-even mergesort, n=8, 19 CE, descending.
__device__ __forceinline__ void sort8_desc(float (&f)[8]) {
    ce(f[0],f[1]); ce(f[2],f[3]); ce(f[4],f[5]); ce(f[6],f[7]);
    ce(f[0],f[2]); ce(f[1],f[3]); ce(f[4],f[6]); ce(f[5],f[7]);
    ce(f[1],f[2]); ce(f[5],f[6]);
    ce(f[0],f[4]); ce(f[1],f[5]); ce(f[2],f[6]); ce(f[3],f[7]);
    ce(f[2],f[4]); ce(f[3],f[5]);
    ce(f[1],f[2]); ce(f[3],f[4]); ce(f[5],f[6]);
}

// Exact sorted top-8 of the union of two descending-sorted 8-lists.
__device__ __forceinline__ void merge8_desc(float (&t)[8], const float (&g)[8]) {
    #pragma unroll
    for (int i = 0; i < 8; ++i) t[i] = fmaxf(t[i], g[7 - i]);
    ce(t[0],t[4]); ce(t[1],t[5]); ce(t[2],t[6]); ce(t[3],t[7]);
    ce(t[0],t[2]); ce(t[1],t[3]); ce(t[4],t[6]); ce(t[5],t[7]);
    ce(t[0],t[1]); ce(t[2],t[3]); ce(t[4],t[5]); ce(t[6],t[7]);
}

// Single-pass kernel: block = (batch, 64-channel group), 512 threads.
// Thread (q, cp) streams S-segment q of channel-pair cp; block merges its
// 16 segments through shared memory. 2 CTAs/SM, 256 blocks = ONE full wave
// at 32 warps/SM.
__global__ __launch_bounds__(NT, 2) void kmax_onepass_kernel(
    const float2* __restrict__ x2, float* __restrict__ out)
{
    __shared__ float s_t[NT][16];               // per-thread t0|t1 (32 KB)

    const int b  = blockIdx.x >> 2;             // / NCG
    const int cg = blockIdx.x & (NCG - 1);
    const int cp = threadIdx.x & (CPB - 1);     // channel-pair within group
    const int q  = threadIdx.x >> 5;            // S-segment index 0..15

    const float2* __restrict__ p =
        x2 + ((size_t)b * S_DIM + (size_t)q * SEG) * (C_DIM / 2) + cg * CPB + cp;

    float t0[8], t1[8];
    #pragma unroll
    for (int i = 0; i < 8; ++i) { t0[i] = -CUDART_INF_F; t1[i] = -CUDART_INF_F; }

    #pragma unroll 1
    for (int s = 0; s < SEG; s += 16) {
        float2 buf[16];
        #pragma unroll
        for (int u = 0; u < 16; ++u)
            buf[u] = __ldcs(p + (size_t)(s + u) * (C_DIM / 2));

        float f[8], g[8];
        // channel .x
        #pragma unroll
        for (int u = 0; u < 8; ++u) { f[u] = buf[u].x; g[u] = buf[u + 8].x; }
        sort8_desc(f); sort8_desc(g);
        merge8_desc(f, g);      // f = sorted top-8 of the 16
        merge8_desc(t0, f);
        // channel .y
        #pragma unroll
        for (int u = 0; u < 8; ++u) { f[u] = buf[u].y; g[u] = buf[u + 8].y; }
        sort8_desc(f); sort8_desc(g);
        merge8_desc(f, g);
        merge8_desc(t1, f);
    }

    // Publish this thread's two sorted top-8s.
    #pragma unroll
    for (int i = 0; i < 8; ++i) {
        s_t[threadIdx.x][i]     = t0[i];
        s_t[threadIdx.x][8 + i] = t1[i];
    }
    __syncthreads();

    // 64 threads merge the 16 q-segment records per channel (64 channels).
    if (threadIdx.x < 64) {
        const int rcp  = threadIdx.x >> 1;      // channel-pair 0..31
        const int half = threadIdx.x & 1;       // 0 = .x, 1 = .y
        const int off  = half * 8;

        float m[8];
        #pragma unroll
        for (int i = 0; i < 8; ++i) m[i] = s_t[rcp][off + i];       // q = 0
        #pragma unroll
        for (int j = 1; j < QDIV; ++j) {
            float g[8];
            #pragma unroll
            for (int i = 0; i < 8; ++i) g[i] = s_t[j * CPB + rcp][off + i];
            merge8_desc(m, g);
        }

        const int ch = cg * (CPB * 2) + rcp * 2 + half;
        float* __restrict__ o = out + (size_t)b * K_TOP * C_DIM + ch;
        #pragma unroll
        for (int k = 0; k < K_TOP; ++k)
            o[(size_t)k * C_DIM] = m[k];
    }
}

extern "C" void kernel_launch(void* const* d_in, const int* in_sizes, int n_in,
                              void* d_out, int out_size) {
    const float2* x2 = (const float2*)d_in[0];
    float* out = (float*)d_out;
    kmax_onepass_kernel<<<GRID1, NT>>>(x2, out);
}